// round 9
// baseline (speedup 1.0000x reference)
#include <cuda_runtime.h>
#include <cstdint>

#define GMAX 64
#define ANCH 2
#define NTHR 128

__global__ void __launch_bounds__(NTHR, 12)
ssd_target_kernel(const float* __restrict__ gt,
                  const int*   __restrict__ cls,
                  const float* __restrict__ anchors,
                  float*       __restrict__ out,
                  int B, int A)
{
    __shared__ float4 s_box [GMAX];   // y1,x1,y2,x2
    __shared__ float4 s_meta[GMAX];   // gcy,gcx,log2(gh),log2(gw)
    __shared__ float  s_area[GMAX];
    __shared__ float  s_cls [GMAX];
    __shared__ int    s_cnt;          // padded count (multiple of 4)

    const int lane = threadIdx.x & 31;
    const int b    = blockIdx.y;      // one batch per block

    // ---- order-preserving compaction of valid GTs (warp 0 only) ----
    if (threadIdx.x < 32) {
        const int gbase = b * GMAX;
        int cnt = 0;
        #pragma unroll
        for (int chunk = 0; chunk < GMAX / 32; ++chunk) {
            const int g = chunk * 32 + lane;
            const float* gp = gt + (size_t)(gbase + g) * 5;
            float y1 = gp[0], x1 = gp[1], y2 = gp[2], x2 = gp[3], tg = gp[4];
            bool valid = (tg != 0.0f);
            unsigned m = __ballot_sync(0xffffffffu, valid);
            int pos = cnt + __popc(m & ((1u << lane) - 1u));
            if (valid) {
                s_box [pos] = make_float4(y1, x1, y2, x2);
                s_area[pos] = __fmul_rn(__fsub_rn(x2, x1), __fsub_rn(y2, y1));
                s_meta[pos] = make_float4((y2 + y1) * 0.5f, (x2 + x1) * 0.5f,
                                          log2f(y2 - y1), log2f(x2 - x1));
                s_cls [pos] = (float)cls[(size_t)(gbase + g) * 2];
            }
            cnt += __popc(m);
        }
        if (lane == 0 && cnt == 0) {
            // reference: argmax over all -1 == index 0; deltas from raw gt[0]
            const float* gp = gt + (size_t)gbase * 5;
            float y1 = gp[0], x1 = gp[1], y2 = gp[2], x2 = gp[3];
            s_box [0] = make_float4(y1, x1, y2, x2);
            s_area[0] = __fmul_rn(__fsub_rn(x2, x1), __fsub_rn(y2, y1));
            s_meta[0] = make_float4((y2 + y1) * 0.5f, (x2 + x1) * 0.5f,
                                    log2f(y2 - y1), log2f(x2 - x1));
            s_cls [0] = (float)cls[(size_t)gbase * 2];
        }
        // pad to multiple of 4 with never-win dummies (inter==0, area==0)
        const int cnt_eff = (cnt == 0) ? 1 : cnt;
        const int cnt_pad = (cnt_eff + 3) & ~3;
        if (lane < cnt_pad - cnt_eff) {
            const int p = cnt_eff + lane;
            s_box [p] = make_float4(0.0f, 0.0f, 0.0f, 0.0f);
            s_area[p] = 0.0f;
            s_cls [p] = 0.0f;
            s_meta[p] = make_float4(0.0f, 0.0f, 0.0f, 0.0f);
        }
        if (lane == 0) s_cnt = cnt_pad;
    }
    __syncthreads();

    const int a0 = blockIdx.x * (NTHR * ANCH) + threadIdx.x;
    const int a1 = a0 + NTHR;
    if (a0 >= A) return;
    const bool has1 = (a1 < A);

    const float4 an0 = __ldg(reinterpret_cast<const float4*>(anchors) + a0);
    const float4 an1 = has1 ? __ldg(reinterpret_cast<const float4*>(anchors) + a1) : an0;
    const float area0 = __fmul_rn(__fsub_rn(an0.w, an0.y), __fsub_rn(an0.z, an0.x));
    const float area1 = __fmul_rn(__fsub_rn(an1.w, an1.y), __fsub_rn(an1.z, an1.x));

    const int cntp = s_cnt;

    // Division/union-free argmax:
    //   iou_j > iou_b  <=>  inter_j * S_b > inter_b * S_j,  S = area_gt + area_an
    // max(0,x)==__saturatef(x) (all extents < 1 -> .SAT folds into the FADD).
    // Dummies (inter=0, area=0) never beat a real/filled entry; real entry 0
    // always beats the -1 sentinel even at inter==0.
    float bi0 = -1.0f, bS0 = 0.0f; int bj0 = 0;   // sentinel: iou = -1/(0-(-1)) = -1
    float bi1 = -1.0f, bS1 = 0.0f; int bj1 = 0;

    #pragma unroll 4
    for (int j = 0; j < cntp; ++j) {
        const float4 g4 = s_box [j];
        const float  ag = s_area[j];
        // anchor 0
        {
            float iw = __saturatef(__fsub_rn(fminf(g4.w, an0.w), fmaxf(g4.y, an0.y)));
            float ih = __saturatef(__fsub_rn(fminf(g4.z, an0.z), fmaxf(g4.x, an0.x)));
            float inter = __fmul_rn(iw, ih);
            float S = __fadd_rn(ag, area0);
            bool better = __fmul_rn(inter, bS0) > __fmul_rn(bi0, S);
            bi0 = better ? inter : bi0;
            bS0 = better ? S     : bS0;
            bj0 = better ? j     : bj0;
        }
        // anchor 1 (independent chain — ILP)
        {
            float iw = __saturatef(__fsub_rn(fminf(g4.w, an1.w), fmaxf(g4.y, an1.y)));
            float ih = __saturatef(__fsub_rn(fminf(g4.z, an1.z), fmaxf(g4.x, an1.x)));
            float inter = __fmul_rn(iw, ih);
            float S = __fadd_rn(ag, area1);
            bool better = __fmul_rn(inter, bS1) > __fmul_rn(bi1, S);
            bi1 = better ? inter : bi1;
            bS1 = better ? S     : bS1;
            bj1 = better ? j     : bj1;
        }
    }

    const size_t N   = (size_t)B * (size_t)A;
    float4* out4 = reinterpret_cast<float4*>(out); // deltas  [0, 4N)
    float*  outc = out + 4 * N;                    // classes [4N, 5N)
    float*  outt = out + 5 * N;                    // tags    [5N, 6N)
    const float KLOG = 3.4657359027997265f;        // ln(2)/0.2 (folds /0.2 BBOX_STD)
    const size_t row = (size_t)b * (size_t)A;

    // ---- epilogue anchor 0 (constants computed here, not loop-live) ----
    {
        const float iou_max = __fdiv_rn(bi0, __fsub_rn(bS0, bi0)); // u = S - inter (ref rounding)
        const float tagv = (iou_max >= 0.5f) ? 1.0f
                          : ((iou_max < 0.4f) ? -1.0f : 0.0f);
        const float4 mt = s_meta[bj0];
        const float ah = an0.z - an0.x, aw = an0.w - an0.y;
        const float acy = (an0.z + an0.x) * 0.5f, acx = (an0.w + an0.y) * 0.5f;
        const float dy = (mt.x - acy) * (10.0f / ah);
        const float dx = (mt.y - acx) * (10.0f / aw);
        const float dh = (mt.z - log2f(ah)) * KLOG;
        const float dw = (mt.w - log2f(aw)) * KLOG;
        const size_t idx = row + (size_t)a0;
        out4[idx] = make_float4(dy, dx, dh, dw);
        outc[idx] = s_cls[bj0];
        outt[idx] = tagv;
    }
    // ---- epilogue anchor 1 ----
    if (has1) {
        const float iou_max = __fdiv_rn(bi1, __fsub_rn(bS1, bi1));
        const float tagv = (iou_max >= 0.5f) ? 1.0f
                          : ((iou_max < 0.4f) ? -1.0f : 0.0f);
        const float4 mt = s_meta[bj1];
        const float ah = an1.z - an1.x, aw = an1.w - an1.y;
        const float acy = (an1.z + an1.x) * 0.5f, acx = (an1.w + an1.y) * 0.5f;
        const float dy = (mt.x - acy) * (10.0f / ah);
        const float dx = (mt.y - acx) * (10.0f / aw);
        const float dh = (mt.z - log2f(ah)) * KLOG;
        const float dw = (mt.w - log2f(aw)) * KLOG;
        const size_t idx = row + (size_t)a1;
        out4[idx] = make_float4(dy, dx, dh, dw);
        outc[idx] = s_cls[bj1];
        outt[idx] = tagv;
    }
}

extern "C" void kernel_launch(void* const* d_in, const int* in_sizes, int n_in,
                              void* d_out, int out_size)
{
    const float* gt      = (const float*)d_in[0];   // [B, 64, 5]
    const int*   cls     = (const int*)  d_in[1];   // [B, 64, 2]
    const float* anchors = (const float*)d_in[2];   // [A, 4]
    float* out = (float*)d_out;

    const int A = in_sizes[2] / 4;
    const int B = in_sizes[0] / (GMAX * 5);

    dim3 grid((A + NTHR * ANCH - 1) / (NTHR * ANCH), B);
    ssd_target_kernel<<<grid, NTHR>>>(gt, cls, anchors, out, B, A);
}

// round 10
// speedup vs baseline: 1.0980x; 1.0980x over previous
#include <cuda_runtime.h>
#include <cstdint>

#define GMAX 64
#define ANCH 2
#define NTHR 128

__global__ void __launch_bounds__(NTHR, 12)
ssd_target_kernel(const float* __restrict__ gt,
                  const int*   __restrict__ cls,
                  const float* __restrict__ anchors,
                  float*       __restrict__ out,
                  int B, int A)
{
    __shared__ float4 s_box [GMAX];                    // y1,x1,y2,x2
    __shared__ float4 s_meta[GMAX];                    // gcy,gcx,log2(gh),log2(gw)
    __shared__ __align__(16) float s_area[GMAX];
    __shared__ float  s_cls [GMAX];
    __shared__ int    s_cnt;                           // padded count (multiple of 4)

    const int lane = threadIdx.x & 31;
    const int b    = blockIdx.y;                       // one batch per block row

    // ---- order-preserving compaction of valid GTs (warp 0 only) ----
    if (threadIdx.x < 32) {
        const int gbase = b * GMAX;
        int cnt = 0;
        #pragma unroll
        for (int chunk = 0; chunk < GMAX / 32; ++chunk) {
            const int g = chunk * 32 + lane;
            const float* gp = gt + (size_t)(gbase + g) * 5;
            float y1 = gp[0], x1 = gp[1], y2 = gp[2], x2 = gp[3], tg = gp[4];
            bool valid = (tg != 0.0f);
            unsigned m = __ballot_sync(0xffffffffu, valid);
            int pos = cnt + __popc(m & ((1u << lane) - 1u));
            if (valid) {
                s_box [pos] = make_float4(y1, x1, y2, x2);
                s_area[pos] = __fmul_rn(__fsub_rn(x2, x1), __fsub_rn(y2, y1));
                s_meta[pos] = make_float4((y2 + y1) * 0.5f, (x2 + x1) * 0.5f,
                                          __log2f(y2 - y1), __log2f(x2 - x1));
                s_cls [pos] = (float)cls[(size_t)(gbase + g) * 2];
            }
            cnt += __popc(m);
        }
        if (lane == 0 && cnt == 0) {
            // reference: argmax over all -1 == index 0; deltas from raw gt[0]
            const float* gp = gt + (size_t)gbase * 5;
            float y1 = gp[0], x1 = gp[1], y2 = gp[2], x2 = gp[3];
            s_box [0] = make_float4(y1, x1, y2, x2);
            s_area[0] = __fmul_rn(__fsub_rn(x2, x1), __fsub_rn(y2, y1));
            s_meta[0] = make_float4((y2 + y1) * 0.5f, (x2 + x1) * 0.5f,
                                    __log2f(y2 - y1), __log2f(x2 - x1));
            s_cls [0] = (float)cls[(size_t)gbase * 2];
        }
        // pad to multiple of 4 with never-win dummies (inter==0, area==0)
        const int cnt_eff = (cnt == 0) ? 1 : cnt;
        const int cnt_pad = (cnt_eff + 3) & ~3;
        if (lane < cnt_pad - cnt_eff) {
            const int p = cnt_eff + lane;
            s_box [p] = make_float4(0.0f, 0.0f, 0.0f, 0.0f);
            s_area[p] = 0.0f;
            s_cls [p] = 0.0f;
            s_meta[p] = make_float4(0.0f, 0.0f, 0.0f, 0.0f);
        }
        if (lane == 0) s_cnt = cnt_pad;
    }
    __syncthreads();

    const int a0 = blockIdx.x * (NTHR * ANCH) + threadIdx.x;
    const int a1 = a0 + NTHR;
    if (a0 >= A) return;
    const bool has1 = (a1 < A);

    const float4 an0 = __ldg(reinterpret_cast<const float4*>(anchors) + a0);
    const float4 an1 = has1 ? __ldg(reinterpret_cast<const float4*>(anchors) + a1) : an0;
    const float area0 = __fmul_rn(__fsub_rn(an0.w, an0.y), __fsub_rn(an0.z, an0.x));
    const float area1 = __fmul_rn(__fsub_rn(an1.w, an1.y), __fsub_rn(an1.z, an1.x));

    const int cntp = s_cnt;

    // Division/union-free argmax:
    //   iou_j > iou_b  <=>  inter_j * S_b > inter_b * S_j,  S = area_gt + area_an
    // max(0,x)==__saturatef(x) (extents < 1 -> .SAT folds into the FADD).
    // Dummies (inter=0, area=0) never beat a real entry; real entry 0 beats
    // the -1 sentinel even at inter==0.
    float bi0 = -1.0f, bS0 = 0.0f; int bj0 = 0;   // sentinel: iou = -1/(0-(-1)) = -1
    float bi1 = -1.0f, bS1 = 0.0f; int bj1 = 0;

    #define PAIR(g4, ag, jj)                                                        \
        {                                                                           \
            float iw0 = __saturatef(__fsub_rn(fminf((g4).w, an0.w),                 \
                                              fmaxf((g4).y, an0.y)));               \
            float ih0 = __saturatef(__fsub_rn(fminf((g4).z, an0.z),                 \
                                              fmaxf((g4).x, an0.x)));               \
            float in0 = __fmul_rn(iw0, ih0);                                        \
            float Sv0 = __fadd_rn((ag), area0);                                     \
            bool bt0 = __fmul_rn(in0, bS0) > __fmul_rn(bi0, Sv0);                   \
            bi0 = bt0 ? in0 : bi0;  bS0 = bt0 ? Sv0 : bS0;  bj0 = bt0 ? (jj) : bj0; \
            float iw1 = __saturatef(__fsub_rn(fminf((g4).w, an1.w),                 \
                                              fmaxf((g4).y, an1.y)));               \
            float ih1 = __saturatef(__fsub_rn(fminf((g4).z, an1.z),                 \
                                              fmaxf((g4).x, an1.x)));               \
            float in1 = __fmul_rn(iw1, ih1);                                        \
            float Sv1 = __fadd_rn((ag), area1);                                     \
            bool bt1 = __fmul_rn(in1, bS1) > __fmul_rn(bi1, Sv1);                   \
            bi1 = bt1 ? in1 : bi1;  bS1 = bt1 ? Sv1 : bS1;  bj1 = bt1 ? (jj) : bj1; \
        }

    for (int j = 0; j < cntp; j += 4) {     // cntp is a multiple of 4: no remainder
        const float4 a4 = *reinterpret_cast<const float4*>(s_area + j);
        const float4 g0 = s_box[j + 0];
        const float4 g1 = s_box[j + 1];
        const float4 g2 = s_box[j + 2];
        const float4 g3 = s_box[j + 3];
        PAIR(g0, a4.x, j + 0)
        PAIR(g1, a4.y, j + 1)
        PAIR(g2, a4.z, j + 2)
        PAIR(g3, a4.w, j + 3)
    }
    #undef PAIR

    const int N = B * A;                            // 1M -> fits int
    float4* out4 = reinterpret_cast<float4*>(out);  // deltas  [0, 4N)
    float*  outc = out + 4 * (size_t)N;             // classes [4N, 5N)
    float*  outt = out + 5 * (size_t)N;             // tags    [5N, 6N)
    const float KLOG = 3.4657359027997265f;         // ln(2)/0.2 (folds /0.2 BBOX_STD)
    const int row = b * A;

    // ---- epilogue anchor 0 (tag path exact; delta path fast-approx, tol 1e-3) ----
    {
        const float iou_max = __fdiv_rn(bi0, __fsub_rn(bS0, bi0)); // u = S - inter
        const float tagv = (iou_max >= 0.5f) ? 1.0f
                          : ((iou_max < 0.4f) ? -1.0f : 0.0f);
        const float4 mt = s_meta[bj0];
        const float ah = an0.z - an0.x, aw = an0.w - an0.y;
        const float acy = (an0.z + an0.x) * 0.5f, acx = (an0.w + an0.y) * 0.5f;
        const float dy = (mt.x - acy) * __fdividef(10.0f, ah);
        const float dx = (mt.y - acx) * __fdividef(10.0f, aw);
        const float dh = (mt.z - __log2f(ah)) * KLOG;
        const float dw = (mt.w - __log2f(aw)) * KLOG;
        const int idx = row + a0;
        out4[idx] = make_float4(dy, dx, dh, dw);
        outc[idx] = s_cls[bj0];
        outt[idx] = tagv;
    }
    // ---- epilogue anchor 1 ----
    if (has1) {
        const float iou_max = __fdiv_rn(bi1, __fsub_rn(bS1, bi1));
        const float tagv = (iou_max >= 0.5f) ? 1.0f
                          : ((iou_max < 0.4f) ? -1.0f : 0.0f);
        const float4 mt = s_meta[bj1];
        const float ah = an1.z - an1.x, aw = an1.w - an1.y;
        const float acy = (an1.z + an1.x) * 0.5f, acx = (an1.w + an1.y) * 0.5f;
        const float dy = (mt.x - acy) * __fdividef(10.0f, ah);
        const float dx = (mt.y - acx) * __fdividef(10.0f, aw);
        const float dh = (mt.z - __log2f(ah)) * KLOG;
        const float dw = (mt.w - __log2f(aw)) * KLOG;
        const int idx = row + a1;
        out4[idx] = make_float4(dy, dx, dh, dw);
        outc[idx] = s_cls[bj1];
        outt[idx] = tagv;
    }
}

extern "C" void kernel_launch(void* const* d_in, const int* in_sizes, int n_in,
                              void* d_out, int out_size)
{
    const float* gt      = (const float*)d_in[0];   // [B, 64, 5]
    const int*   cls     = (const int*)  d_in[1];   // [B, 64, 2]
    const float* anchors = (const float*)d_in[2];   // [A, 4]
    float* out = (float*)d_out;

    const int A = in_sizes[2] / 4;
    const int B = in_sizes[0] / (GMAX * 5);

    dim3 grid((A + NTHR * ANCH - 1) / (NTHR * ANCH), B);
    ssd_target_kernel<<<grid, NTHR>>>(gt, cls, anchors, out, B, A);
}